// round 1
// baseline (speedup 1.0000x reference)
#include <cuda_runtime.h>

#define NN 100000
#define NE 3200000
#define NG 256

// ---------------- static scratch (no allocations allowed) ----------------
__device__ int   g_deg[NN];
__device__ int   g_rowptr[NN + 1];
__device__ int   g_cursor[NN];
__device__ int2  g_csrcv[NE];          // (col, val-bits) interleaved CSR
__device__ float g_tmp5[NN * 5];       // spmm(x) output, 5-dim
__device__ float4 g_xcur[NN * 16];     // current layer features [NN,64]
__device__ float4 g_spmm[NN * 16];     // spmm output buffer   [NN,64]
__device__ float4 g_hsum[NN * 16];     // x1+x2+x3 accumulator [NN,64]
__device__ float g_pool[NG * 64];
__device__ float g_cnt[NG];

// ---------------- zero scratch that is accumulated into ----------------
__global__ void zero_kernel() {
    int i = blockIdx.x * blockDim.x + threadIdx.x;
    if (i < NN) g_deg[i] = 0;
    if (i < NG * 64) g_pool[i] = 0.f;
    if (i < NG) g_cnt[i] = 0.f;
}

// ---------------- CSR build ----------------
__global__ void hist_kernel(const int* __restrict__ rows) {
    int e = blockIdx.x * blockDim.x + threadIdx.x;
    if (e < NE) atomicAdd(&g_deg[rows[e]], 1);
}

__global__ void scan_kernel() {   // 1 block, 1024 threads
    __shared__ int s[1024];
    int t = threadIdx.x;
    const int CH = (NN + 1023) / 1024;      // 98
    int beg = t * CH;
    int end = beg + CH; if (end > NN) end = NN;
    if (beg > NN) beg = NN;
    int sum = 0;
    for (int i = beg; i < end; i++) sum += g_deg[i];
    s[t] = sum;
    __syncthreads();
    for (int off = 1; off < 1024; off <<= 1) {
        int v = 0;
        if (t >= off) v = s[t - off];
        __syncthreads();
        if (t >= off) s[t] += v;
        __syncthreads();
    }
    int run = (t == 0) ? 0 : s[t - 1];
    for (int i = beg; i < end; i++) {
        g_rowptr[i] = run;
        g_cursor[i] = run;
        run += g_deg[i];
    }
    if (t == 1023) g_rowptr[NN] = s[1023];
}

__global__ void scatter_kernel(const int* __restrict__ rows,
                               const int* __restrict__ cols,
                               const float* __restrict__ vals) {
    int e = blockIdx.x * blockDim.x + threadIdx.x;
    if (e < NE) {
        int r = rows[e];
        int p = atomicAdd(&g_cursor[r], 1);
        g_csrcv[p] = make_int2(cols[e], __float_as_int(vals[e]));
    }
}

// ---------------- SPMM on 5-dim input ----------------
__global__ void spmm5_kernel(const float* __restrict__ x) {
    int r = blockIdx.x * blockDim.x + threadIdx.x;
    if (r >= NN) return;
    float a0 = 0, a1 = 0, a2 = 0, a3 = 0, a4 = 0;
    int e = g_rowptr[r], end = g_rowptr[r + 1];
    for (; e < end; e++) {
        int2 cv = g_csrcv[e];
        float v = __int_as_float(cv.y);
        const float* xr = x + (long)cv.x * 5;
        a0 += v * xr[0];
        a1 += v * xr[1];
        a2 += v * xr[2];
        a3 += v * xr[3];
        a4 += v * xr[4];
    }
    float* o = g_tmp5 + (long)r * 5;
    o[0] = a0; o[1] = a1; o[2] = a2; o[3] = a3; o[4] = a4;
}

// ---------------- Linear 5->64 + ReLU; writes xcur and hsum= ----------------
__global__ void lin1_kernel(const float* __restrict__ W1, const float* __restrict__ b1) {
    __shared__ float Ws[5 * 64];
    __shared__ float bs[64];
    int tid = threadIdx.x;
    for (int i = tid; i < 5 * 64; i += blockDim.x) Ws[i] = W1[i];
    if (tid < 64) bs[tid] = b1[tid];
    __syncthreads();
    int gt = blockIdx.x * blockDim.x + tid;       // NN*32 threads
    int node = gt >> 5;
    int lane = gt & 31;
    const float* in = g_tmp5 + (long)node * 5;
    float i0 = in[0], i1 = in[1], i2 = in[2], i3 = in[3], i4 = in[4];
    int o0 = lane, o1 = lane + 32;
    float a0 = bs[o0] + i0 * Ws[o0] + i1 * Ws[64 + o0] + i2 * Ws[128 + o0]
             + i3 * Ws[192 + o0] + i4 * Ws[256 + o0];
    float a1 = bs[o1] + i0 * Ws[o1] + i1 * Ws[64 + o1] + i2 * Ws[128 + o1]
             + i3 * Ws[192 + o1] + i4 * Ws[256 + o1];
    a0 = fmaxf(a0, 0.f);
    a1 = fmaxf(a1, 0.f);
    float* xc = (float*)g_xcur;
    float* hs = (float*)g_hsum;
    xc[(long)node * 64 + o0] = a0;
    xc[(long)node * 64 + o1] = a1;
    hs[(long)node * 64 + o0] = a0;
    hs[(long)node * 64 + o1] = a1;
}

// ---------------- SPMM 64-dim: xcur -> spmm ----------------
// 16 lanes per row, each lane owns a float4 of features.
__global__ void spmm64_kernel() {
    int f = threadIdx.x;                         // 0..15
    int row = blockIdx.x * 16 + threadIdx.y;
    if (row >= NN) return;
    const float4* __restrict__ xin = g_xcur;
    int e = g_rowptr[row], end = g_rowptr[row + 1];
    float4 acc = make_float4(0.f, 0.f, 0.f, 0.f);
    for (; e + 2 <= end; e += 2) {
        int2 c0 = g_csrcv[e];
        int2 c1 = g_csrcv[e + 1];
        float4 a = xin[(long)c0.x * 16 + f];
        float4 b = xin[(long)c1.x * 16 + f];
        float v0 = __int_as_float(c0.y);
        float v1 = __int_as_float(c1.y);
        acc.x += v0 * a.x; acc.y += v0 * a.y; acc.z += v0 * a.z; acc.w += v0 * a.w;
        acc.x += v1 * b.x; acc.y += v1 * b.y; acc.z += v1 * b.z; acc.w += v1 * b.w;
    }
    if (e < end) {
        int2 c0 = g_csrcv[e];
        float4 a = xin[(long)c0.x * 16 + f];
        float v0 = __int_as_float(c0.y);
        acc.x += v0 * a.x; acc.y += v0 * a.y; acc.z += v0 * a.z; acc.w += v0 * a.w;
    }
    g_spmm[(long)row * 16 + f] = acc;
}

// ---------------- Linear 64->64 + ReLU: spmm -> xcur, hsum += ----------------
// Block: 256 threads, 64 nodes. W in smem, input tile staged in padded smem.
// Thread = (node n, output quarter q): 16 outputs as 4 float4 accumulators.
__global__ void lin64_kernel(const float* __restrict__ W, const float* __restrict__ b) {
    __shared__ float4 Ws4[64 * 16];        // 16 KB
    __shared__ float  bs[64];
    __shared__ float  ins[64 * 68];        // padded rows (stride 68) ~17 KB
    int tid = threadIdx.x;
    const float4* W4 = (const float4*)W;
    for (int i = tid; i < 64 * 16; i += 256) Ws4[i] = W4[i];
    if (tid < 64) bs[tid] = b[tid];
    int base = blockIdx.x * 64;
    for (int i = tid; i < 64 * 16; i += 256) {
        int n = i >> 4, kc = i & 15;
        int node = base + n;
        float4 v = (node < NN) ? g_spmm[(long)node * 16 + kc]
                               : make_float4(0.f, 0.f, 0.f, 0.f);
        *(float4*)&ins[n * 68 + kc * 4] = v;
    }
    __syncthreads();
    int n = tid >> 2;
    int q = tid & 3;
    int node = base + n;
    float4 acc0 = make_float4(bs[q * 16 + 0], bs[q * 16 + 1], bs[q * 16 + 2], bs[q * 16 + 3]);
    float4 acc1 = make_float4(bs[q * 16 + 4], bs[q * 16 + 5], bs[q * 16 + 6], bs[q * 16 + 7]);
    float4 acc2 = make_float4(bs[q * 16 + 8], bs[q * 16 + 9], bs[q * 16 + 10], bs[q * 16 + 11]);
    float4 acc3 = make_float4(bs[q * 16 + 12], bs[q * 16 + 13], bs[q * 16 + 14], bs[q * 16 + 15]);
#pragma unroll 4
    for (int k = 0; k < 64; k++) {
        float xk = ins[n * 68 + k];
        float4 w0 = Ws4[k * 16 + q * 4 + 0];
        float4 w1 = Ws4[k * 16 + q * 4 + 1];
        float4 w2 = Ws4[k * 16 + q * 4 + 2];
        float4 w3 = Ws4[k * 16 + q * 4 + 3];
        acc0.x += xk * w0.x; acc0.y += xk * w0.y; acc0.z += xk * w0.z; acc0.w += xk * w0.w;
        acc1.x += xk * w1.x; acc1.y += xk * w1.y; acc1.z += xk * w1.z; acc1.w += xk * w1.w;
        acc2.x += xk * w2.x; acc2.y += xk * w2.y; acc2.z += xk * w2.z; acc2.w += xk * w2.w;
        acc3.x += xk * w3.x; acc3.y += xk * w3.y; acc3.z += xk * w3.z; acc3.w += xk * w3.w;
    }
    if (node < NN) {
        acc0.x = fmaxf(acc0.x, 0.f); acc0.y = fmaxf(acc0.y, 0.f); acc0.z = fmaxf(acc0.z, 0.f); acc0.w = fmaxf(acc0.w, 0.f);
        acc1.x = fmaxf(acc1.x, 0.f); acc1.y = fmaxf(acc1.y, 0.f); acc1.z = fmaxf(acc1.z, 0.f); acc1.w = fmaxf(acc1.w, 0.f);
        acc2.x = fmaxf(acc2.x, 0.f); acc2.y = fmaxf(acc2.y, 0.f); acc2.z = fmaxf(acc2.z, 0.f); acc2.w = fmaxf(acc2.w, 0.f);
        acc3.x = fmaxf(acc3.x, 0.f); acc3.y = fmaxf(acc3.y, 0.f); acc3.z = fmaxf(acc3.z, 0.f); acc3.w = fmaxf(acc3.w, 0.f);
        long ob = (long)node * 16 + q * 4;
        g_xcur[ob + 0] = acc0; g_xcur[ob + 1] = acc1;
        g_xcur[ob + 2] = acc2; g_xcur[ob + 3] = acc3;
        float4 h;
        h = g_hsum[ob + 0]; h.x += acc0.x; h.y += acc0.y; h.z += acc0.z; h.w += acc0.w; g_hsum[ob + 0] = h;
        h = g_hsum[ob + 1]; h.x += acc1.x; h.y += acc1.y; h.z += acc1.z; h.w += acc1.w; g_hsum[ob + 1] = h;
        h = g_hsum[ob + 2]; h.x += acc2.x; h.y += acc2.y; h.z += acc2.z; h.w += acc2.w; g_hsum[ob + 2] = h;
        h = g_hsum[ob + 3]; h.x += acc3.x; h.y += acc3.y; h.z += acc3.z; h.w += acc3.w; g_hsum[ob + 3] = h;
    }
}

// ---------------- mean-pool over sorted batch (run-length + boundary atomics) ----
__global__ void pool_kernel(const int* __restrict__ batch) {
    int f = threadIdx.x;            // 0..63
    int ty = threadIdx.y;           // 0..3
    int base = blockIdx.x * 512;
    const float* hs = (const float*)g_hsum;
    float accum = 0.f;
    int gcur = -1;
    int cnt = 0;
    for (int i = ty; i < 512; i += 4) {
        int nd = base + i;
        if (nd >= NN) break;
        int g = batch[nd];
        if (g != gcur) {
            if (gcur >= 0) {
                atomicAdd(&g_pool[gcur * 64 + f], accum);
                if (f == 0) atomicAdd(&g_cnt[gcur], (float)cnt);
            }
            gcur = g; accum = 0.f; cnt = 0;
        }
        accum += hs[(long)nd * 64 + f];
        cnt++;
    }
    if (gcur >= 0) {
        atomicAdd(&g_pool[gcur * 64 + f], accum);
        if (f == 0) atomicAdd(&g_cnt[gcur], (float)cnt);
    }
}

// ---------------- final linear 64->10 + softmax ----------------
__global__ void final_kernel(const float* __restrict__ Wl, const float* __restrict__ bl,
                             float* __restrict__ out) {
    __shared__ float Ws[64 * 10];
    __shared__ float bs[10];
    int tid = threadIdx.x;           // 256 threads, one graph each
    for (int i = tid; i < 640; i += 256) Ws[i] = Wl[i];
    if (tid < 10) bs[tid] = bl[tid];
    __syncthreads();
    int g = tid;
    float cnt = g_cnt[g];
    float inv = 1.0f / (3.0f * fmaxf(cnt, 1.0f));
    float logits[10];
#pragma unroll
    for (int o = 0; o < 10; o++) logits[o] = bs[o];
    for (int f = 0; f < 64; f++) {
        float m = g_pool[g * 64 + f] * inv;
#pragma unroll
        for (int o = 0; o < 10; o++) logits[o] += m * Ws[f * 10 + o];
    }
    float mx = logits[0];
#pragma unroll
    for (int o = 1; o < 10; o++) mx = fmaxf(mx, logits[o]);
    float sum = 0.f;
#pragma unroll
    for (int o = 0; o < 10; o++) { logits[o] = expf(logits[o] - mx); sum += logits[o]; }
    float is = 1.0f / sum;
#pragma unroll
    for (int o = 0; o < 10; o++) out[g * 10 + o] = logits[o] * is;
}

// ---------------- launch ----------------
extern "C" void kernel_launch(void* const* d_in, const int* in_sizes, int n_in,
                              void* d_out, int out_size) {
    const float* x    = (const float*)d_in[0];
    const int*   rows = (const int*)d_in[1];
    const int*   cols = (const int*)d_in[2];
    const float* vals = (const float*)d_in[3];
    const int*   batch= (const int*)d_in[4];
    const float* W1 = (const float*)d_in[5];
    const float* b1 = (const float*)d_in[6];
    const float* W2 = (const float*)d_in[7];
    const float* b2 = (const float*)d_in[8];
    const float* W3 = (const float*)d_in[9];
    const float* b3 = (const float*)d_in[10];
    const float* Wl = (const float*)d_in[11];
    const float* bl = (const float*)d_in[12];
    float* out = (float*)d_out;

    zero_kernel<<<(NN + 255) / 256, 256>>>();
    hist_kernel<<<(NE + 255) / 256, 256>>>(rows);
    scan_kernel<<<1, 1024>>>();
    scatter_kernel<<<(NE + 255) / 256, 256>>>(rows, cols, vals);

    spmm5_kernel<<<(NN + 255) / 256, 256>>>(x);
    lin1_kernel<<<(NN * 32) / 256, 256>>>(W1, b1);

    spmm64_kernel<<<(NN + 15) / 16, dim3(16, 16)>>>();
    lin64_kernel<<<(NN + 63) / 64, 256>>>(W2, b2);

    spmm64_kernel<<<(NN + 15) / 16, dim3(16, 16)>>>();
    lin64_kernel<<<(NN + 63) / 64, 256>>>(W3, b3);

    pool_kernel<<<(NN + 511) / 512, dim3(64, 4)>>>(batch);
    final_kernel<<<1, 256>>>(Wl, bl, out);
}

// round 2
// speedup vs baseline: 1.0615x; 1.0615x over previous
#include <cuda_runtime.h>
#include <cuda_fp16.h>

#define NN 100000
#define NE 3200000
#define NG 256

// ---------------- static scratch ----------------
__device__ int   g_deg[NN];
__device__ int   g_rowptr[NN + 1];
__device__ int   g_cursor[NN];
__device__ int2  g_csrcv[NE];          // (col, val-bits) interleaved CSR
__device__ float g_tmp5[NN * 5];       // spmm(x) output, 5-dim
__device__ uint4 g_xh[NN * 8];         // fp16 features [NN,64], 8 halves per uint4
__device__ float4 g_spmm[NN * 16];     // spmm output (fp32) [NN,64]
__device__ float g_hsum[NN * 64];      // x1+x2+x3 accumulator (fp32)
__device__ float g_pool[NG * 64];
__device__ float g_cnt[NG];

// ---------------- zero ----------------
__global__ void zero_kernel() {
    int i = blockIdx.x * blockDim.x + threadIdx.x;
    if (i < NN) g_deg[i] = 0;
    if (i < NG * 64) g_pool[i] = 0.f;
    if (i < NG) g_cnt[i] = 0.f;
}

// ---------------- CSR build ----------------
__global__ void hist_kernel(const int4* __restrict__ rows4) {
    int i = blockIdx.x * blockDim.x + threadIdx.x;
    if (i < NE / 4) {
        int4 r = rows4[i];
        atomicAdd(&g_deg[r.x], 1);
        atomicAdd(&g_deg[r.y], 1);
        atomicAdd(&g_deg[r.z], 1);
        atomicAdd(&g_deg[r.w], 1);
    }
}

__global__ void scan_kernel() {   // 1 block, 1024 threads
    __shared__ int s[1024];
    int t = threadIdx.x;
    const int CH = (NN + 1023) / 1024;
    int beg = t * CH;
    int end = beg + CH; if (end > NN) end = NN;
    if (beg > NN) beg = NN;
    int sum = 0;
    for (int i = beg; i < end; i++) sum += g_deg[i];
    s[t] = sum;
    __syncthreads();
    for (int off = 1; off < 1024; off <<= 1) {
        int v = 0;
        if (t >= off) v = s[t - off];
        __syncthreads();
        if (t >= off) s[t] += v;
        __syncthreads();
    }
    int run = (t == 0) ? 0 : s[t - 1];
    for (int i = beg; i < end; i++) {
        g_rowptr[i] = run;
        g_cursor[i] = run;
        run += g_deg[i];
    }
    if (t == 1023) g_rowptr[NN] = s[1023];
}

__global__ void scatter_kernel(const int4* __restrict__ rows4,
                               const int4* __restrict__ cols4,
                               const float4* __restrict__ vals4) {
    int i = blockIdx.x * blockDim.x + threadIdx.x;
    if (i < NE / 4) {
        int4 r = rows4[i];
        int4 c = cols4[i];
        float4 v = vals4[i];
        int p;
        p = atomicAdd(&g_cursor[r.x], 1); g_csrcv[p] = make_int2(c.x, __float_as_int(v.x));
        p = atomicAdd(&g_cursor[r.y], 1); g_csrcv[p] = make_int2(c.y, __float_as_int(v.y));
        p = atomicAdd(&g_cursor[r.z], 1); g_csrcv[p] = make_int2(c.z, __float_as_int(v.z));
        p = atomicAdd(&g_cursor[r.w], 1); g_csrcv[p] = make_int2(c.w, __float_as_int(v.w));
    }
}

// ---------------- SPMM on 5-dim input ----------------
__global__ void spmm5_kernel(const float* __restrict__ x) {
    int r = blockIdx.x * blockDim.x + threadIdx.x;
    if (r >= NN) return;
    float a0 = 0, a1 = 0, a2 = 0, a3 = 0, a4 = 0;
    int e = g_rowptr[r], end = g_rowptr[r + 1];
    for (; e < end; e++) {
        int2 cv = g_csrcv[e];
        float v = __int_as_float(cv.y);
        const float* xr = x + (long)cv.x * 5;
        a0 += v * xr[0];
        a1 += v * xr[1];
        a2 += v * xr[2];
        a3 += v * xr[3];
        a4 += v * xr[4];
    }
    float* o = g_tmp5 + (long)r * 5;
    o[0] = a0; o[1] = a1; o[2] = a2; o[3] = a3; o[4] = a4;
}

// ---------------- Linear 5->64 + ReLU: tmp5 -> xh (fp16), hsum = ----------------
__global__ void lin1_kernel(const float* __restrict__ W1, const float* __restrict__ b1) {
    __shared__ float Ws[5 * 64];
    __shared__ float bs[64];
    int tid = threadIdx.x;
    for (int i = tid; i < 5 * 64; i += blockDim.x) Ws[i] = W1[i];
    if (tid < 64) bs[tid] = b1[tid];
    __syncthreads();
    int gt = blockIdx.x * blockDim.x + tid;       // NN*32 threads
    int node = gt >> 5;
    int lane = gt & 31;
    const float* in = g_tmp5 + (long)node * 5;
    float i0 = in[0], i1 = in[1], i2 = in[2], i3 = in[3], i4 = in[4];
    int o0 = lane * 2, o1 = lane * 2 + 1;
    float a0 = bs[o0] + i0 * Ws[o0] + i1 * Ws[64 + o0] + i2 * Ws[128 + o0]
             + i3 * Ws[192 + o0] + i4 * Ws[256 + o0];
    float a1 = bs[o1] + i0 * Ws[o1] + i1 * Ws[64 + o1] + i2 * Ws[128 + o1]
             + i3 * Ws[192 + o1] + i4 * Ws[256 + o1];
    a0 = fmaxf(a0, 0.f);
    a1 = fmaxf(a1, 0.f);
    ((__half2*)g_xh)[(long)node * 32 + lane] = __floats2half2_rn(a0, a1);
    ((float2*)g_hsum)[(long)node * 32 + lane] = make_float2(a0, a1);
}

// ---------------- SPMM 64-dim (fp16 gather): xh -> spmm (fp32) ----------------
// 8 lanes per row; each lane owns 8 features (one uint4 of halves).
__global__ void spmm64_kernel() {
    int f = threadIdx.x & 7;
    int row = blockIdx.x * 32 + (threadIdx.x >> 3);
    const uint4* __restrict__ xin = g_xh;
    int e = g_rowptr[row], end = g_rowptr[row + 1];
    float acc[8];
#pragma unroll
    for (int j = 0; j < 8; j++) acc[j] = 0.f;
    for (; e + 2 <= end; e += 2) {
        int2 c0 = g_csrcv[e];
        int2 c1 = g_csrcv[e + 1];
        uint4 a = xin[(long)c0.x * 8 + f];
        uint4 b = xin[(long)c1.x * 8 + f];
        float v0 = __int_as_float(c0.y);
        float v1 = __int_as_float(c1.y);
        float2 p;
        p = __half22float2(*(__half2*)&a.x); acc[0] += v0 * p.x; acc[1] += v0 * p.y;
        p = __half22float2(*(__half2*)&a.y); acc[2] += v0 * p.x; acc[3] += v0 * p.y;
        p = __half22float2(*(__half2*)&a.z); acc[4] += v0 * p.x; acc[5] += v0 * p.y;
        p = __half22float2(*(__half2*)&a.w); acc[6] += v0 * p.x; acc[7] += v0 * p.y;
        p = __half22float2(*(__half2*)&b.x); acc[0] += v1 * p.x; acc[1] += v1 * p.y;
        p = __half22float2(*(__half2*)&b.y); acc[2] += v1 * p.x; acc[3] += v1 * p.y;
        p = __half22float2(*(__half2*)&b.z); acc[4] += v1 * p.x; acc[5] += v1 * p.y;
        p = __half22float2(*(__half2*)&b.w); acc[6] += v1 * p.x; acc[7] += v1 * p.y;
    }
    if (e < end) {
        int2 c0 = g_csrcv[e];
        uint4 a = xin[(long)c0.x * 8 + f];
        float v0 = __int_as_float(c0.y);
        float2 p;
        p = __half22float2(*(__half2*)&a.x); acc[0] += v0 * p.x; acc[1] += v0 * p.y;
        p = __half22float2(*(__half2*)&a.y); acc[2] += v0 * p.x; acc[3] += v0 * p.y;
        p = __half22float2(*(__half2*)&a.z); acc[4] += v0 * p.x; acc[5] += v0 * p.y;
        p = __half22float2(*(__half2*)&a.w); acc[6] += v0 * p.x; acc[7] += v0 * p.y;
    }
    long ob = (long)row * 16 + f * 2;
    g_spmm[ob + 0] = make_float4(acc[0], acc[1], acc[2], acc[3]);
    g_spmm[ob + 1] = make_float4(acc[4], acc[5], acc[6], acc[7]);
}

// ---------------- Linear 64->64 + ReLU: spmm -> xh (fp16), hsum += ----------------
template <bool WRITE_X>
__global__ void lin64_kernel(const float* __restrict__ W, const float* __restrict__ b) {
    __shared__ float4 Ws4[64 * 16];        // 16 KB
    __shared__ float  bs[64];
    __shared__ float  ins[64 * 68];        // padded rows (stride 68)
    int tid = threadIdx.x;
    const float4* W4 = (const float4*)W;
    for (int i = tid; i < 64 * 16; i += 256) Ws4[i] = W4[i];
    if (tid < 64) bs[tid] = b[tid];
    int base = blockIdx.x * 64;
    for (int i = tid; i < 64 * 16; i += 256) {
        int n = i >> 4, kc = i & 15;
        int node = base + n;
        float4 v = (node < NN) ? g_spmm[(long)node * 16 + kc]
                               : make_float4(0.f, 0.f, 0.f, 0.f);
        *(float4*)&ins[n * 68 + kc * 4] = v;
    }
    __syncthreads();
    int n = tid >> 2;
    int q = tid & 3;
    int node = base + n;
    float4 acc0 = make_float4(bs[q * 16 + 0], bs[q * 16 + 1], bs[q * 16 + 2], bs[q * 16 + 3]);
    float4 acc1 = make_float4(bs[q * 16 + 4], bs[q * 16 + 5], bs[q * 16 + 6], bs[q * 16 + 7]);
    float4 acc2 = make_float4(bs[q * 16 + 8], bs[q * 16 + 9], bs[q * 16 + 10], bs[q * 16 + 11]);
    float4 acc3 = make_float4(bs[q * 16 + 12], bs[q * 16 + 13], bs[q * 16 + 14], bs[q * 16 + 15]);
#pragma unroll 4
    for (int k = 0; k < 64; k++) {
        float xk = ins[n * 68 + k];
        float4 w0 = Ws4[k * 16 + q * 4 + 0];
        float4 w1 = Ws4[k * 16 + q * 4 + 1];
        float4 w2 = Ws4[k * 16 + q * 4 + 2];
        float4 w3 = Ws4[k * 16 + q * 4 + 3];
        acc0.x += xk * w0.x; acc0.y += xk * w0.y; acc0.z += xk * w0.z; acc0.w += xk * w0.w;
        acc1.x += xk * w1.x; acc1.y += xk * w1.y; acc1.z += xk * w1.z; acc1.w += xk * w1.w;
        acc2.x += xk * w2.x; acc2.y += xk * w2.y; acc2.z += xk * w2.z; acc2.w += xk * w2.w;
        acc3.x += xk * w3.x; acc3.y += xk * w3.y; acc3.z += xk * w3.z; acc3.w += xk * w3.w;
    }
    if (node < NN) {
        acc0.x = fmaxf(acc0.x, 0.f); acc0.y = fmaxf(acc0.y, 0.f); acc0.z = fmaxf(acc0.z, 0.f); acc0.w = fmaxf(acc0.w, 0.f);
        acc1.x = fmaxf(acc1.x, 0.f); acc1.y = fmaxf(acc1.y, 0.f); acc1.z = fmaxf(acc1.z, 0.f); acc1.w = fmaxf(acc1.w, 0.f);
        acc2.x = fmaxf(acc2.x, 0.f); acc2.y = fmaxf(acc2.y, 0.f); acc2.z = fmaxf(acc2.z, 0.f); acc2.w = fmaxf(acc2.w, 0.f);
        acc3.x = fmaxf(acc3.x, 0.f); acc3.y = fmaxf(acc3.y, 0.f); acc3.z = fmaxf(acc3.z, 0.f); acc3.w = fmaxf(acc3.w, 0.f);
        if (WRITE_X) {
            uint4 h0, h1;
            *(__half2*)&h0.x = __floats2half2_rn(acc0.x, acc0.y);
            *(__half2*)&h0.y = __floats2half2_rn(acc0.z, acc0.w);
            *(__half2*)&h0.z = __floats2half2_rn(acc1.x, acc1.y);
            *(__half2*)&h0.w = __floats2half2_rn(acc1.z, acc1.w);
            *(__half2*)&h1.x = __floats2half2_rn(acc2.x, acc2.y);
            *(__half2*)&h1.y = __floats2half2_rn(acc2.z, acc2.w);
            *(__half2*)&h1.z = __floats2half2_rn(acc3.x, acc3.y);
            *(__half2*)&h1.w = __floats2half2_rn(acc3.z, acc3.w);
            g_xh[(long)node * 8 + q * 2 + 0] = h0;
            g_xh[(long)node * 8 + q * 2 + 1] = h1;
        }
        float4* hsum4 = (float4*)g_hsum;
        long ob = (long)node * 16 + q * 4;
        float4 h;
        h = hsum4[ob + 0]; h.x += acc0.x; h.y += acc0.y; h.z += acc0.z; h.w += acc0.w; hsum4[ob + 0] = h;
        h = hsum4[ob + 1]; h.x += acc1.x; h.y += acc1.y; h.z += acc1.z; h.w += acc1.w; hsum4[ob + 1] = h;
        h = hsum4[ob + 2]; h.x += acc2.x; h.y += acc2.y; h.z += acc2.z; h.w += acc2.w; hsum4[ob + 2] = h;
        h = hsum4[ob + 3]; h.x += acc3.x; h.y += acc3.y; h.z += acc3.z; h.w += acc3.w; hsum4[ob + 3] = h;
    }
}

// ---------------- mean-pool over sorted batch ----------------
__global__ void pool_kernel(const int* __restrict__ batch) {
    int f = threadIdx.x;            // 0..63
    int ty = threadIdx.y;           // 0..3
    int base = blockIdx.x * 512;
    const float* hs = g_hsum;
    float accum = 0.f;
    int gcur = -1;
    int cnt = 0;
    for (int i = ty; i < 512; i += 4) {
        int nd = base + i;
        if (nd >= NN) break;
        int g = batch[nd];
        if (g != gcur) {
            if (gcur >= 0) {
                atomicAdd(&g_pool[gcur * 64 + f], accum);
                if (f == 0) atomicAdd(&g_cnt[gcur], (float)cnt);
            }
            gcur = g; accum = 0.f; cnt = 0;
        }
        accum += hs[(long)nd * 64 + f];
        cnt++;
    }
    if (gcur >= 0) {
        atomicAdd(&g_pool[gcur * 64 + f], accum);
        if (f == 0) atomicAdd(&g_cnt[gcur], (float)cnt);
    }
}

// ---------------- final linear 64->10 + softmax ----------------
__global__ void final_kernel(const float* __restrict__ Wl, const float* __restrict__ bl,
                             float* __restrict__ out) {
    __shared__ float Ws[64 * 10];
    __shared__ float bs[10];
    int tid = threadIdx.x;           // 256 threads, one graph each
    for (int i = tid; i < 640; i += 256) Ws[i] = Wl[i];
    if (tid < 10) bs[tid] = bl[tid];
    __syncthreads();
    int g = tid;
    float cnt = g_cnt[g];
    float inv = 1.0f / (3.0f * fmaxf(cnt, 1.0f));
    float logits[10];
#pragma unroll
    for (int o = 0; o < 10; o++) logits[o] = bs[o];
    for (int f = 0; f < 64; f++) {
        float m = g_pool[g * 64 + f] * inv;
#pragma unroll
        for (int o = 0; o < 10; o++) logits[o] += m * Ws[f * 10 + o];
    }
    float mx = logits[0];
#pragma unroll
    for (int o = 1; o < 10; o++) mx = fmaxf(mx, logits[o]);
    float sum = 0.f;
#pragma unroll
    for (int o = 0; o < 10; o++) { logits[o] = expf(logits[o] - mx); sum += logits[o]; }
    float is = 1.0f / sum;
#pragma unroll
    for (int o = 0; o < 10; o++) out[g * 10 + o] = logits[o] * is;
}

// ---------------- launch ----------------
extern "C" void kernel_launch(void* const* d_in, const int* in_sizes, int n_in,
                              void* d_out, int out_size) {
    const float* x    = (const float*)d_in[0];
    const int*   rows = (const int*)d_in[1];
    const int*   cols = (const int*)d_in[2];
    const float* vals = (const float*)d_in[3];
    const int*   batch= (const int*)d_in[4];
    const float* W1 = (const float*)d_in[5];
    const float* b1 = (const float*)d_in[6];
    const float* W2 = (const float*)d_in[7];
    const float* b2 = (const float*)d_in[8];
    const float* W3 = (const float*)d_in[9];
    const float* b3 = (const float*)d_in[10];
    const float* Wl = (const float*)d_in[11];
    const float* bl = (const float*)d_in[12];
    float* out = (float*)d_out;

    zero_kernel<<<(NN + 255) / 256, 256>>>();
    hist_kernel<<<(NE / 4 + 255) / 256, 256>>>((const int4*)rows);
    scan_kernel<<<1, 1024>>>();
    scatter_kernel<<<(NE / 4 + 255) / 256, 256>>>((const int4*)rows, (const int4*)cols,
                                                  (const float4*)vals);

    spmm5_kernel<<<(NN + 255) / 256, 256>>>(x);
    lin1_kernel<<<(NN * 32) / 256, 256>>>(W1, b1);

    spmm64_kernel<<<(NN + 31) / 32, 256>>>();
    lin64_kernel<true><<<(NN + 63) / 64, 256>>>(W2, b2);

    spmm64_kernel<<<(NN + 31) / 32, 256>>>();
    lin64_kernel<false><<<(NN + 63) / 64, 256>>>(W3, b3);

    pool_kernel<<<(NN + 511) / 512, dim3(64, 4)>>>(batch);
    final_kernel<<<1, 256>>>(Wl, bl, out);
}

// round 3
// speedup vs baseline: 1.5556x; 1.4655x over previous
#include <cuda_runtime.h>
#include <cuda_fp16.h>

#define NN 100000
#define NE 3200000
#define NG 256
#define NB_SCAN 196   // ceil(NN/512)

// ---------------- static scratch ----------------
__device__ int    g_deg[NN];
__device__ int    g_rowptr[NN + 1];
__device__ int    g_cursor[NN];
__device__ int    g_bsum[NB_SCAN];
__device__ int    g_boff[NB_SCAN];
__device__ int2   g_csrcv[NE];         // (col, val-bits) interleaved CSR
__device__ uint4  g_xha[NN * 8];       // fp16 features A [NN,64]
__device__ uint4  g_xhb[NN * 8];       // fp16 features B [NN,64]
__device__ float4 g_spmm[NN * 16];     // spmm output (fp32) [NN,64]
__device__ float  g_hsum[NN * 64];     // x1+x2(+x3) accumulator (fp32)
__device__ float  g_pool[NG * 64];

// ---------------- zero ----------------
__global__ void zero_kernel() {
    int i = blockIdx.x * blockDim.x + threadIdx.x;
    if (i < NN) g_deg[i] = 0;
    if (i < NG * 64) g_pool[i] = 0.f;
}

// ---------------- CSR build ----------------
__global__ void hist_kernel(const int4* __restrict__ rows4) {
    int i = blockIdx.x * blockDim.x + threadIdx.x;
    if (i < NE / 4) {
        int4 r = rows4[i];
        atomicAdd(&g_deg[r.x], 1);
        atomicAdd(&g_deg[r.y], 1);
        atomicAdd(&g_deg[r.z], 1);
        atomicAdd(&g_deg[r.w], 1);
    }
}

// stage A: per-block partial sums of g_deg (512 elems / block)
__global__ void scanA_kernel() {
    __shared__ int s[512];
    int t = threadIdx.x;
    int i = blockIdx.x * 512 + t;
    s[t] = (i < NN) ? g_deg[i] : 0;
    __syncthreads();
    for (int off = 256; off > 0; off >>= 1) {
        if (t < off) s[t] += s[t + off];
        __syncthreads();
    }
    if (t == 0) g_bsum[blockIdx.x] = s[0];
}

// stage B: exclusive scan of 196 block sums (1 block)
__global__ void scanB_kernel() {
    __shared__ int s[256];
    int t = threadIdx.x;
    s[t] = (t < NB_SCAN) ? g_bsum[t] : 0;
    __syncthreads();
    for (int off = 1; off < 256; off <<= 1) {
        int v = 0;
        if (t >= off) v = s[t - off];
        __syncthreads();
        if (t >= off) s[t] += v;
        __syncthreads();
    }
    if (t < NB_SCAN) g_boff[t] = (t == 0) ? 0 : s[t - 1];
}

// stage C: in-block exclusive scan + offset -> rowptr, cursor
__global__ void scanC_kernel() {
    __shared__ int s[512];
    int t = threadIdx.x;
    int i = blockIdx.x * 512 + t;
    int d = (i < NN) ? g_deg[i] : 0;
    s[t] = d;
    __syncthreads();
    for (int off = 1; off < 512; off <<= 1) {
        int v = 0;
        if (t >= off) v = s[t - off];
        __syncthreads();
        if (t >= off) s[t] += v;
        __syncthreads();
    }
    int incl = s[t];
    int base = g_boff[blockIdx.x];
    if (i < NN) {
        int p = base + incl - d;
        g_rowptr[i] = p;
        g_cursor[i] = p;
        if (i == NN - 1) g_rowptr[NN] = base + incl;
    }
}

__global__ void scatter_kernel(const int4* __restrict__ rows4,
                               const int4* __restrict__ cols4,
                               const float4* __restrict__ vals4) {
    int i = blockIdx.x * blockDim.x + threadIdx.x;
    if (i < NE / 4) {
        int4 r = rows4[i];
        int4 c = cols4[i];
        float4 v = vals4[i];
        int p;
        p = atomicAdd(&g_cursor[r.x], 1); g_csrcv[p] = make_int2(c.x, __float_as_int(v.x));
        p = atomicAdd(&g_cursor[r.y], 1); g_csrcv[p] = make_int2(c.y, __float_as_int(v.y));
        p = atomicAdd(&g_cursor[r.z], 1); g_csrcv[p] = make_int2(c.z, __float_as_int(v.z));
        p = atomicAdd(&g_cursor[r.w], 1); g_csrcv[p] = make_int2(c.w, __float_as_int(v.w));
    }
}

// ---------------- pre-GEMM: z0 = x @ W1 (no bias) -> g_xha (fp16) ----------------
__global__ void pregemm_kernel(const float* __restrict__ x, const float* __restrict__ W1) {
    __shared__ float4 Ws4[5 * 16];   // W1 [5][64] as float4
    int tid = threadIdx.x;
    if (tid < 80) Ws4[tid] = ((const float4*)W1)[tid];
    __syncthreads();
    int n = blockIdx.x * blockDim.x + tid;
    if (n >= NN) return;
    const float* xr = x + (long)n * 5;
    float i0 = xr[0], i1 = xr[1], i2 = xr[2], i3 = xr[3], i4 = xr[4];
    uint4 outv[8];
#pragma unroll
    for (int j = 0; j < 8; j++) {       // 8 features-pairs groups: j covers feats 8j..8j+7
#pragma unroll
        for (int hp = 0; hp < 2; hp++) { // two float4 per uint4
            int g4 = j * 2 + hp;         // float4 index (feats 4*g4..)
            float4 w0 = Ws4[0 * 16 + g4];
            float4 w1 = Ws4[1 * 16 + g4];
            float4 w2 = Ws4[2 * 16 + g4];
            float4 w3 = Ws4[3 * 16 + g4];
            float4 w4 = Ws4[4 * 16 + g4];
            float a0 = i0 * w0.x + i1 * w1.x + i2 * w2.x + i3 * w3.x + i4 * w4.x;
            float a1 = i0 * w0.y + i1 * w1.y + i2 * w2.y + i3 * w3.y + i4 * w4.y;
            float a2 = i0 * w0.z + i1 * w1.z + i2 * w2.z + i3 * w3.z + i4 * w4.z;
            float a3 = i0 * w0.w + i1 * w1.w + i2 * w2.w + i3 * w3.w + i4 * w4.w;
            ((__half2*)&outv[j])[hp * 2 + 0] = __floats2half2_rn(a0, a1);
            ((__half2*)&outv[j])[hp * 2 + 1] = __floats2half2_rn(a2, a3);
        }
    }
#pragma unroll
    for (int j = 0; j < 8; j++) g_xha[(long)n * 8 + j] = outv[j];
}

// ---------------- SPMM 64-dim fp16 gather, MLP-4 unroll ----------------
// MODE 0: src=g_xha, epilogue = +b1, relu -> g_xhb (fp16) + g_hsum (fp32 init)
// MODE 1: src=g_xhb, plain fp32 -> g_spmm
// MODE 2: src=g_xha, plain fp32 -> g_spmm
__device__ __forceinline__ void fma_edge(float* acc, uint4 a, float v) {
    float2 p;
    p = __half22float2(*(__half2*)&a.x); acc[0] += v * p.x; acc[1] += v * p.y;
    p = __half22float2(*(__half2*)&a.y); acc[2] += v * p.x; acc[3] += v * p.y;
    p = __half22float2(*(__half2*)&a.z); acc[4] += v * p.x; acc[5] += v * p.y;
    p = __half22float2(*(__half2*)&a.w); acc[6] += v * p.x; acc[7] += v * p.y;
}

template <int MODE>
__global__ void spmm64_kernel(const float* __restrict__ b1) {
    int f = threadIdx.x & 7;
    int row = blockIdx.x * 32 + (threadIdx.x >> 3);
    if (row >= NN) return;
    const uint4* __restrict__ xin = (MODE == 1) ? g_xhb : g_xha;
    int e = g_rowptr[row], end = g_rowptr[row + 1];
    float acc[8];
#pragma unroll
    for (int j = 0; j < 8; j++) acc[j] = 0.f;
    for (; e + 4 <= end; e += 4) {
        int2 c0 = g_csrcv[e];
        int2 c1 = g_csrcv[e + 1];
        int2 c2 = g_csrcv[e + 2];
        int2 c3 = g_csrcv[e + 3];
        uint4 a0 = xin[(long)c0.x * 8 + f];
        uint4 a1 = xin[(long)c1.x * 8 + f];
        uint4 a2 = xin[(long)c2.x * 8 + f];
        uint4 a3 = xin[(long)c3.x * 8 + f];
        fma_edge(acc, a0, __int_as_float(c0.y));
        fma_edge(acc, a1, __int_as_float(c1.y));
        fma_edge(acc, a2, __int_as_float(c2.y));
        fma_edge(acc, a3, __int_as_float(c3.y));
    }
    for (; e < end; e++) {
        int2 c0 = g_csrcv[e];
        uint4 a0 = xin[(long)c0.x * 8 + f];
        fma_edge(acc, a0, __int_as_float(c0.y));
    }
    if (MODE == 0) {
        float4 bA = ((const float4*)b1)[f * 2];
        float4 bB = ((const float4*)b1)[f * 2 + 1];
        float r0 = fmaxf(acc[0] + bA.x, 0.f);
        float r1 = fmaxf(acc[1] + bA.y, 0.f);
        float r2 = fmaxf(acc[2] + bA.z, 0.f);
        float r3 = fmaxf(acc[3] + bA.w, 0.f);
        float r4 = fmaxf(acc[4] + bB.x, 0.f);
        float r5 = fmaxf(acc[5] + bB.y, 0.f);
        float r6 = fmaxf(acc[6] + bB.z, 0.f);
        float r7 = fmaxf(acc[7] + bB.w, 0.f);
        uint4 h;
        *(__half2*)&h.x = __floats2half2_rn(r0, r1);
        *(__half2*)&h.y = __floats2half2_rn(r2, r3);
        *(__half2*)&h.z = __floats2half2_rn(r4, r5);
        *(__half2*)&h.w = __floats2half2_rn(r6, r7);
        g_xhb[(long)row * 8 + f] = h;
        float4* hs = (float4*)(g_hsum + (long)row * 64 + f * 8);
        hs[0] = make_float4(r0, r1, r2, r3);
        hs[1] = make_float4(r4, r5, r6, r7);
    } else {
        long ob = (long)row * 16 + f * 2;
        g_spmm[ob + 0] = make_float4(acc[0], acc[1], acc[2], acc[3]);
        g_spmm[ob + 1] = make_float4(acc[4], acc[5], acc[6], acc[7]);
    }
}

// ---------------- Linear 64->64 + ReLU ----------------
// WRITE_X=true : g_spmm -> relu(...) -> g_xha (fp16), g_hsum +=
// WRITE_X=false: g_spmm -> relu(...) + g_hsum -> in-block pooling -> g_pool atomics
template <bool WRITE_X>
__global__ void lin64_kernel(const float* __restrict__ W, const float* __restrict__ b,
                             const int* __restrict__ batch) {
    __shared__ float4 Ws4[64 * 16];        // 16 KB
    __shared__ float  bs[64];
    __shared__ float  ins[64 * 68];        // padded rows
    __shared__ int    sb[64];
    int tid = threadIdx.x;
    const float4* W4 = (const float4*)W;
    for (int i = tid; i < 64 * 16; i += 256) Ws4[i] = W4[i];
    if (tid < 64) bs[tid] = b[tid];
    int base = blockIdx.x * 64;
    if (!WRITE_X) {
        if (tid < 64) {
            int nd = base + tid;
            sb[tid] = batch[nd < NN ? nd : (NN - 1)];
        }
    }
    for (int i = tid; i < 64 * 16; i += 256) {
        int n = i >> 4, kc = i & 15;
        int node = base + n;
        float4 v = (node < NN) ? g_spmm[(long)node * 16 + kc]
                               : make_float4(0.f, 0.f, 0.f, 0.f);
        *(float4*)&ins[n * 68 + kc * 4] = v;
    }
    __syncthreads();
    int n = tid >> 2;
    int q = tid & 3;
    int node = base + n;
    float4 acc0 = make_float4(bs[q * 16 + 0], bs[q * 16 + 1], bs[q * 16 + 2], bs[q * 16 + 3]);
    float4 acc1 = make_float4(bs[q * 16 + 4], bs[q * 16 + 5], bs[q * 16 + 6], bs[q * 16 + 7]);
    float4 acc2 = make_float4(bs[q * 16 + 8], bs[q * 16 + 9], bs[q * 16 + 10], bs[q * 16 + 11]);
    float4 acc3 = make_float4(bs[q * 16 + 12], bs[q * 16 + 13], bs[q * 16 + 14], bs[q * 16 + 15]);
#pragma unroll 4
    for (int k = 0; k < 64; k++) {
        float xk = ins[n * 68 + k];
        float4 w0 = Ws4[k * 16 + q * 4 + 0];
        float4 w1 = Ws4[k * 16 + q * 4 + 1];
        float4 w2 = Ws4[k * 16 + q * 4 + 2];
        float4 w3 = Ws4[k * 16 + q * 4 + 3];
        acc0.x += xk * w0.x; acc0.y += xk * w0.y; acc0.z += xk * w0.z; acc0.w += xk * w0.w;
        acc1.x += xk * w1.x; acc1.y += xk * w1.y; acc1.z += xk * w1.z; acc1.w += xk * w1.w;
        acc2.x += xk * w2.x; acc2.y += xk * w2.y; acc2.z += xk * w2.z; acc2.w += xk * w2.w;
        acc3.x += xk * w3.x; acc3.y += xk * w3.y; acc3.z += xk * w3.z; acc3.w += xk * w3.w;
    }
    acc0.x = fmaxf(acc0.x, 0.f); acc0.y = fmaxf(acc0.y, 0.f); acc0.z = fmaxf(acc0.z, 0.f); acc0.w = fmaxf(acc0.w, 0.f);
    acc1.x = fmaxf(acc1.x, 0.f); acc1.y = fmaxf(acc1.y, 0.f); acc1.z = fmaxf(acc1.z, 0.f); acc1.w = fmaxf(acc1.w, 0.f);
    acc2.x = fmaxf(acc2.x, 0.f); acc2.y = fmaxf(acc2.y, 0.f); acc2.z = fmaxf(acc2.z, 0.f); acc2.w = fmaxf(acc2.w, 0.f);
    acc3.x = fmaxf(acc3.x, 0.f); acc3.y = fmaxf(acc3.y, 0.f); acc3.z = fmaxf(acc3.z, 0.f); acc3.w = fmaxf(acc3.w, 0.f);

    if (WRITE_X) {
        if (node < NN) {
            uint4 h0, h1;
            *(__half2*)&h0.x = __floats2half2_rn(acc0.x, acc0.y);
            *(__half2*)&h0.y = __floats2half2_rn(acc0.z, acc0.w);
            *(__half2*)&h0.z = __floats2half2_rn(acc1.x, acc1.y);
            *(__half2*)&h0.w = __floats2half2_rn(acc1.z, acc1.w);
            *(__half2*)&h1.x = __floats2half2_rn(acc2.x, acc2.y);
            *(__half2*)&h1.y = __floats2half2_rn(acc2.z, acc2.w);
            *(__half2*)&h1.z = __floats2half2_rn(acc3.x, acc3.y);
            *(__half2*)&h1.w = __floats2half2_rn(acc3.z, acc3.w);
            g_xha[(long)node * 8 + q * 2 + 0] = h0;
            g_xha[(long)node * 8 + q * 2 + 1] = h1;
            float4* hsum4 = (float4*)g_hsum;
            long ob = (long)node * 16 + q * 4;
            float4 h;
            h = hsum4[ob + 0]; h.x += acc0.x; h.y += acc0.y; h.z += acc0.z; h.w += acc0.w; hsum4[ob + 0] = h;
            h = hsum4[ob + 1]; h.x += acc1.x; h.y += acc1.y; h.z += acc1.z; h.w += acc1.w; hsum4[ob + 1] = h;
            h = hsum4[ob + 2]; h.x += acc2.x; h.y += acc2.y; h.z += acc2.z; h.w += acc2.w; hsum4[ob + 2] = h;
            h = hsum4[ob + 3]; h.x += acc3.x; h.y += acc3.y; h.z += acc3.z; h.w += acc3.w; hsum4[ob + 3] = h;
        }
    } else {
        // h = hsum_prev + x3 ; stash transposed into ins, then segmented pool
        float4 h0 = make_float4(0, 0, 0, 0), h1 = h0, h2 = h0, h3 = h0;
        if (node < NN) {
            const float4* hsum4 = (const float4*)g_hsum;
            long ob = (long)node * 16 + q * 4;
            float4 p0 = hsum4[ob + 0], p1 = hsum4[ob + 1], p2 = hsum4[ob + 2], p3 = hsum4[ob + 3];
            h0 = make_float4(p0.x + acc0.x, p0.y + acc0.y, p0.z + acc0.z, p0.w + acc0.w);
            h1 = make_float4(p1.x + acc1.x, p1.y + acc1.y, p1.z + acc1.z, p1.w + acc1.w);
            h2 = make_float4(p2.x + acc2.x, p2.y + acc2.y, p2.z + acc2.z, p2.w + acc2.w);
            h3 = make_float4(p3.x + acc3.x, p3.y + acc3.y, p3.z + acc3.z, p3.w + acc3.w);
        }
        __syncthreads();   // done reading ins as matmul input
        *(float4*)&ins[n * 68 + q * 16 + 0]  = h0;
        *(float4*)&ins[n * 68 + q * 16 + 4]  = h1;
        *(float4*)&ins[n * 68 + q * 16 + 8]  = h2;
        *(float4*)&ins[n * 68 + q * 16 + 12] = h3;
        __syncthreads();
        if (tid < 64) {
            int fidx = tid;
            float accum = 0.f;
            int gcur = sb[0];
            for (int nn = 0; nn < 64; nn++) {
                int g = sb[nn];
                if (g != gcur) {
                    atomicAdd(&g_pool[gcur * 64 + fidx], accum);
                    gcur = g; accum = 0.f;
                }
                accum += ins[nn * 68 + fidx];
            }
            atomicAdd(&g_pool[gcur * 64 + fidx], accum);
        }
    }
}

// ---------------- final linear 64->10 + softmax (counts via binary search) -------
__global__ void final_kernel(const int* __restrict__ batch,
                             const float* __restrict__ Wl, const float* __restrict__ bl,
                             float* __restrict__ out) {
    __shared__ float Ws[64 * 10];
    __shared__ float bs[10];
    int tid = threadIdx.x;           // 256 threads, one graph each
    for (int i = tid; i < 640; i += 256) Ws[i] = Wl[i];
    if (tid < 10) bs[tid] = bl[tid];
    __syncthreads();
    int g = tid;
    // lower_bound(g): first idx with batch[idx] >= g
    int lo = 0, hi = NN;
    while (lo < hi) { int mid = (lo + hi) >> 1; if (batch[mid] < g) lo = mid + 1; else hi = mid; }
    int lb = lo;
    lo = 0; hi = NN;
    while (lo < hi) { int mid = (lo + hi) >> 1; if (batch[mid] < g + 1) lo = mid + 1; else hi = mid; }
    float cnt = (float)(lo - lb);
    float inv = 1.0f / (3.0f * fmaxf(cnt, 1.0f));
    float logits[10];
#pragma unroll
    for (int o = 0; o < 10; o++) logits[o] = bs[o];
    for (int f = 0; f < 64; f++) {
        float m = g_pool[g * 64 + f] * inv;
#pragma unroll
        for (int o = 0; o < 10; o++) logits[o] += m * Ws[f * 10 + o];
    }
    float mx = logits[0];
#pragma unroll
    for (int o = 1; o < 10; o++) mx = fmaxf(mx, logits[o]);
    float sum = 0.f;
#pragma unroll
    for (int o = 0; o < 10; o++) { logits[o] = expf(logits[o] - mx); sum += logits[o]; }
    float is = 1.0f / sum;
#pragma unroll
    for (int o = 0; o < 10; o++) out[g * 10 + o] = logits[o] * is;
}

// ---------------- launch ----------------
extern "C" void kernel_launch(void* const* d_in, const int* in_sizes, int n_in,
                              void* d_out, int out_size) {
    const float* x    = (const float*)d_in[0];
    const int*   rows = (const int*)d_in[1];
    const int*   cols = (const int*)d_in[2];
    const float* vals = (const float*)d_in[3];
    const int*   batch= (const int*)d_in[4];
    const float* W1 = (const float*)d_in[5];
    const float* b1 = (const float*)d_in[6];
    const float* W2 = (const float*)d_in[7];
    const float* b2 = (const float*)d_in[8];
    const float* W3 = (const float*)d_in[9];
    const float* b3 = (const float*)d_in[10];
    const float* Wl = (const float*)d_in[11];
    const float* bl = (const float*)d_in[12];
    float* out = (float*)d_out;

    zero_kernel<<<(NN + 255) / 256, 256>>>();
    hist_kernel<<<(NE / 4 + 255) / 256, 256>>>((const int4*)rows);
    scanA_kernel<<<NB_SCAN, 512>>>();
    scanB_kernel<<<1, 256>>>();
    scanC_kernel<<<NB_SCAN, 512>>>();
    scatter_kernel<<<(NE / 4 + 255) / 256, 256>>>((const int4*)rows, (const int4*)cols,
                                                  (const float4*)vals);

    pregemm_kernel<<<(NN + 255) / 256, 256>>>(x, W1);

    spmm64_kernel<0><<<(NN + 31) / 32, 256>>>(b1);          // xha -> xhb(+b1,relu), hsum=x1
    spmm64_kernel<1><<<(NN + 31) / 32, 256>>>(nullptr);     // xhb -> g_spmm
    lin64_kernel<true><<<(NN + 63) / 64, 256>>>(W2, b2, batch);   // -> xha, hsum+=x2
    spmm64_kernel<2><<<(NN + 31) / 32, 256>>>(nullptr);     // xha -> g_spmm
    lin64_kernel<false><<<(NN + 63) / 64, 256>>>(W3, b3, batch);  // + hsum -> pool

    final_kernel<<<1, 256>>>(batch, Wl, bl, out);
}

// round 4
// speedup vs baseline: 1.6865x; 1.0841x over previous
#include <cuda_runtime.h>
#include <cuda_fp16.h>

#define NN 100000
#define NE 3200000
#define NG 256
#define NB_SCAN 196   // ceil(NN/512)

// ---------------- static scratch ----------------
__device__ int    g_deg[NN];
__device__ int    g_rowptr[NN + 1];
__device__ int    g_cursor[NN];
__device__ int    g_bsum[NB_SCAN];
__device__ int    g_boff[NB_SCAN];
__device__ int2   g_csrcv[NE];         // (col, val-bits) interleaved CSR
__device__ uint4  g_xha[NN * 8];       // fp16 features A [NN,64]
__device__ uint4  g_xhb[NN * 8];       // fp16 features B [NN,64]
__device__ float  g_pool[NG * 64];

// ---------------- f32x2 helpers ----------------
static __forceinline__ __device__ unsigned long long pk2(float lo, float hi) {
    unsigned long long r;
    asm("mov.b64 %0,{%1,%2};" : "=l"(r) : "f"(lo), "f"(hi));
    return r;
}
static __forceinline__ __device__ unsigned long long fma2(unsigned long long a,
                                                          unsigned long long b,
                                                          unsigned long long c) {
    unsigned long long d;
    asm("fma.rn.f32x2 %0,%1,%2,%3;" : "=l"(d) : "l"(a), "l"(b), "l"(c));
    return d;
}
static __forceinline__ __device__ void upk2(unsigned long long v, float& lo, float& hi) {
    asm("mov.b64 {%0,%1},%2;" : "=f"(lo), "=f"(hi) : "l"(v));
}

// ---------------- zero ----------------
__global__ void zero_kernel() {
    int i = blockIdx.x * blockDim.x + threadIdx.x;
    if (i < NN) g_deg[i] = 0;
    if (i < NG * 64) g_pool[i] = 0.f;
}

// ---------------- CSR build ----------------
__global__ void hist_kernel(const int4* __restrict__ rows4) {
    int i = blockIdx.x * blockDim.x + threadIdx.x;
    if (i < NE / 4) {
        int4 r = rows4[i];
        atomicAdd(&g_deg[r.x], 1);
        atomicAdd(&g_deg[r.y], 1);
        atomicAdd(&g_deg[r.z], 1);
        atomicAdd(&g_deg[r.w], 1);
    }
}

__global__ void scanA_kernel() {
    __shared__ int s[512];
    int t = threadIdx.x;
    int i = blockIdx.x * 512 + t;
    s[t] = (i < NN) ? g_deg[i] : 0;
    __syncthreads();
    for (int off = 256; off > 0; off >>= 1) {
        if (t < off) s[t] += s[t + off];
        __syncthreads();
    }
    if (t == 0) g_bsum[blockIdx.x] = s[0];
}

__global__ void scanB_kernel() {
    __shared__ int s[256];
    int t = threadIdx.x;
    s[t] = (t < NB_SCAN) ? g_bsum[t] : 0;
    __syncthreads();
    for (int off = 1; off < 256; off <<= 1) {
        int v = 0;
        if (t >= off) v = s[t - off];
        __syncthreads();
        if (t >= off) s[t] += v;
        __syncthreads();
    }
    if (t < NB_SCAN) g_boff[t] = (t == 0) ? 0 : s[t - 1];
}

__global__ void scanC_kernel() {
    __shared__ int s[512];
    int t = threadIdx.x;
    int i = blockIdx.x * 512 + t;
    int d = (i < NN) ? g_deg[i] : 0;
    s[t] = d;
    __syncthreads();
    for (int off = 1; off < 512; off <<= 1) {
        int v = 0;
        if (t >= off) v = s[t - off];
        __syncthreads();
        if (t >= off) s[t] += v;
        __syncthreads();
    }
    int incl = s[t];
    int base = g_boff[blockIdx.x];
    if (i < NN) {
        int p = base + incl - d;
        g_rowptr[i] = p;
        g_cursor[i] = p;
        if (i == NN - 1) g_rowptr[NN] = base + incl;
    }
}

__global__ void scatter_kernel(const int4* __restrict__ rows4,
                               const int4* __restrict__ cols4,
                               const float4* __restrict__ vals4) {
    int i = blockIdx.x * blockDim.x + threadIdx.x;
    if (i < NE / 4) {
        int4 r = rows4[i];
        int4 c = cols4[i];
        float4 v = vals4[i];
        int p;
        p = atomicAdd(&g_cursor[r.x], 1); g_csrcv[p] = make_int2(c.x, __float_as_int(v.x));
        p = atomicAdd(&g_cursor[r.y], 1); g_csrcv[p] = make_int2(c.y, __float_as_int(v.y));
        p = atomicAdd(&g_cursor[r.z], 1); g_csrcv[p] = make_int2(c.z, __float_as_int(v.z));
        p = atomicAdd(&g_cursor[r.w], 1); g_csrcv[p] = make_int2(c.w, __float_as_int(v.w));
    }
}

// ---------------- pre-GEMM: z0 = x @ W1 (no bias) -> g_xha (fp16) ----------------
__global__ void pregemm_kernel(const float* __restrict__ x, const float* __restrict__ W1) {
    __shared__ float4 Ws4[5 * 16];
    int tid = threadIdx.x;
    if (tid < 80) Ws4[tid] = ((const float4*)W1)[tid];
    __syncthreads();
    int n = blockIdx.x * blockDim.x + tid;
    if (n >= NN) return;
    const float* xr = x + (long)n * 5;
    float i0 = xr[0], i1 = xr[1], i2 = xr[2], i3 = xr[3], i4 = xr[4];
    uint4 outv[8];
#pragma unroll
    for (int j = 0; j < 8; j++) {
#pragma unroll
        for (int hp = 0; hp < 2; hp++) {
            int g4 = j * 2 + hp;
            float4 w0 = Ws4[0 * 16 + g4];
            float4 w1 = Ws4[1 * 16 + g4];
            float4 w2 = Ws4[2 * 16 + g4];
            float4 w3 = Ws4[3 * 16 + g4];
            float4 w4 = Ws4[4 * 16 + g4];
            float a0 = i0 * w0.x + i1 * w1.x + i2 * w2.x + i3 * w3.x + i4 * w4.x;
            float a1 = i0 * w0.y + i1 * w1.y + i2 * w2.y + i3 * w3.y + i4 * w4.y;
            float a2 = i0 * w0.z + i1 * w1.z + i2 * w2.z + i3 * w3.z + i4 * w4.z;
            float a3 = i0 * w0.w + i1 * w1.w + i2 * w2.w + i3 * w3.w + i4 * w4.w;
            ((__half2*)&outv[j])[hp * 2 + 0] = __floats2half2_rn(a0, a1);
            ((__half2*)&outv[j])[hp * 2 + 1] = __floats2half2_rn(a2, a3);
        }
    }
#pragma unroll
    for (int j = 0; j < 8; j++) g_xha[(long)n * 8 + j] = outv[j];
}

// ---------------- spmm gather core ----------------
__device__ __forceinline__ void fma_edge(float* acc, uint4 a, float v) {
    float2 p;
    p = __half22float2(*(__half2*)&a.x); acc[0] += v * p.x; acc[1] += v * p.y;
    p = __half22float2(*(__half2*)&a.y); acc[2] += v * p.x; acc[3] += v * p.y;
    p = __half22float2(*(__half2*)&a.z); acc[4] += v * p.x; acc[5] += v * p.y;
    p = __half22float2(*(__half2*)&a.w); acc[6] += v * p.x; acc[7] += v * p.y;
}

__device__ __forceinline__ void gather_row(const uint4* __restrict__ xin,
                                           int row, int f, float* acc) {
#pragma unroll
    for (int j = 0; j < 8; j++) acc[j] = 0.f;
    int e = g_rowptr[row], end = g_rowptr[row + 1];
    for (; e + 4 <= end; e += 4) {
        int2 c0 = g_csrcv[e];
        int2 c1 = g_csrcv[e + 1];
        int2 c2 = g_csrcv[e + 2];
        int2 c3 = g_csrcv[e + 3];
        uint4 a0 = xin[(long)c0.x * 8 + f];
        uint4 a1 = xin[(long)c1.x * 8 + f];
        uint4 a2 = xin[(long)c2.x * 8 + f];
        uint4 a3 = xin[(long)c3.x * 8 + f];
        fma_edge(acc, a0, __int_as_float(c0.y));
        fma_edge(acc, a1, __int_as_float(c1.y));
        fma_edge(acc, a2, __int_as_float(c2.y));
        fma_edge(acc, a3, __int_as_float(c3.y));
    }
    for (; e < end; e++) {
        int2 c0 = g_csrcv[e];
        uint4 a0 = xin[(long)c0.x * 8 + f];
        fma_edge(acc, a0, __int_as_float(c0.y));
    }
}

// ---------------- layer 1: spmm(xha) + b1, relu -> xhb (fp16) + pool x1 ----------
// 256 threads, 32 rows/block, 8 lanes/row
__global__ void spmm_l1_kernel(const float* __restrict__ b1, const int* __restrict__ batch) {
    __shared__ float sp[32 * 68];
    __shared__ int   sb[32];
    int tid = threadIdx.x;
    int f = tid & 7;
    int r = tid >> 3;               // 0..31
    int base = blockIdx.x * 32;
    int row = base + r;
    if (tid < 32) {
        int nd = base + tid;
        sb[tid] = batch[nd < NN ? nd : (NN - 1)];
    }
    float acc[8];
    if (row < NN) {
        gather_row(g_xha, row, f, acc);
        float4 bA = ((const float4*)b1)[f * 2];
        float4 bB = ((const float4*)b1)[f * 2 + 1];
        acc[0] = fmaxf(acc[0] + bA.x, 0.f);
        acc[1] = fmaxf(acc[1] + bA.y, 0.f);
        acc[2] = fmaxf(acc[2] + bA.z, 0.f);
        acc[3] = fmaxf(acc[3] + bA.w, 0.f);
        acc[4] = fmaxf(acc[4] + bB.x, 0.f);
        acc[5] = fmaxf(acc[5] + bB.y, 0.f);
        acc[6] = fmaxf(acc[6] + bB.z, 0.f);
        acc[7] = fmaxf(acc[7] + bB.w, 0.f);
        uint4 h;
        *(__half2*)&h.x = __floats2half2_rn(acc[0], acc[1]);
        *(__half2*)&h.y = __floats2half2_rn(acc[2], acc[3]);
        *(__half2*)&h.z = __floats2half2_rn(acc[4], acc[5]);
        *(__half2*)&h.w = __floats2half2_rn(acc[6], acc[7]);
        g_xhb[(long)row * 8 + f] = h;
    } else {
#pragma unroll
        for (int j = 0; j < 8; j++) acc[j] = 0.f;
    }
    *(float4*)&sp[r * 68 + f * 8 + 0] = make_float4(acc[0], acc[1], acc[2], acc[3]);
    *(float4*)&sp[r * 68 + f * 8 + 4] = make_float4(acc[4], acc[5], acc[6], acc[7]);
    __syncthreads();
    if (tid < 64) {
        int rows_here = NN - base; if (rows_here > 32) rows_here = 32;
        float accum = 0.f;
        int gcur = sb[0];
        for (int nn = 0; nn < rows_here; nn++) {
            int g = sb[nn];
            if (g != gcur) {
                atomicAdd(&g_pool[gcur * 64 + tid], accum);
                gcur = g; accum = 0.f;
            }
            accum += sp[nn * 68 + tid];
        }
        if (rows_here > 0) atomicAdd(&g_pool[gcur * 64 + tid], accum);
    }
}

// ---------------- fused spmm + linear 64->64 + relu + pool ----------------
// 512 threads, 64 rows/block. SRC=0: gather xhb, write xha. SRC=1: gather xha, no write.
template <int SRC>
__global__ void __launch_bounds__(512, 4)
spmm_lin_kernel(const float* __restrict__ W, const float* __restrict__ b,
                const int* __restrict__ batch) {
    __shared__ float Ws[64 * 64];    // 16 KB, row-major [k][o]
    __shared__ float bs[64];
    __shared__ float ins[64 * 68];   // ~17.4 KB
    __shared__ int   sb[64];
    int tid = threadIdx.x;
    for (int i = tid; i < 64 * 16; i += 512) ((float4*)Ws)[i] = ((const float4*)W)[i];
    if (tid < 64) bs[tid] = b[tid];
    int base = blockIdx.x * 64;
    if (tid >= 448 && tid < 512) {
        int nd = base + (tid - 448);
        sb[tid - 448] = batch[nd < NN ? nd : (NN - 1)];
    }
    // ---- gather phase: lane f, row r ----
    {
        int f = tid & 7;
        int r = tid >> 3;            // 0..63
        int row = base + r;
        float acc[8];
        if (row < NN) {
            gather_row(SRC == 0 ? g_xhb : g_xha, row, f, acc);
        } else {
#pragma unroll
            for (int j = 0; j < 8; j++) acc[j] = 0.f;
        }
        *(float4*)&ins[r * 68 + f * 8 + 0] = make_float4(acc[0], acc[1], acc[2], acc[3]);
        *(float4*)&ins[r * 68 + f * 8 + 4] = make_float4(acc[4], acc[5], acc[6], acc[7]);
    }
    __syncthreads();
    // ---- GEMM phase: thread = (row n, output octet q) ----
    int n = tid >> 3;
    int q = tid & 7;
    int node = base + n;
    unsigned long long a0 = pk2(bs[q * 8 + 0], bs[q * 8 + 1]);
    unsigned long long a1 = pk2(bs[q * 8 + 2], bs[q * 8 + 3]);
    unsigned long long a2 = pk2(bs[q * 8 + 4], bs[q * 8 + 5]);
    unsigned long long a3 = pk2(bs[q * 8 + 6], bs[q * 8 + 7]);
    const ulonglong2* W64 = (const ulonglong2*)Ws;
#pragma unroll 8
    for (int k = 0; k < 64; k++) {
        float xk = ins[n * 68 + k];
        unsigned long long xk2 = pk2(xk, xk);
        ulonglong2 w01 = W64[k * 16 + q * 2];
        ulonglong2 w23 = W64[k * 16 + q * 2 + 1];
        a0 = fma2(xk2, w01.x, a0);
        a1 = fma2(xk2, w01.y, a1);
        a2 = fma2(xk2, w23.x, a2);
        a3 = fma2(xk2, w23.y, a3);
    }
    float o[8];
    upk2(a0, o[0], o[1]);
    upk2(a1, o[2], o[3]);
    upk2(a2, o[4], o[5]);
    upk2(a3, o[6], o[7]);
#pragma unroll
    for (int j = 0; j < 8; j++) o[j] = fmaxf(o[j], 0.f);
    if (SRC == 0 && node < NN) {
        uint4 h;
        *(__half2*)&h.x = __floats2half2_rn(o[0], o[1]);
        *(__half2*)&h.y = __floats2half2_rn(o[2], o[3]);
        *(__half2*)&h.z = __floats2half2_rn(o[4], o[5]);
        *(__half2*)&h.w = __floats2half2_rn(o[6], o[7]);
        g_xha[(long)node * 8 + q] = h;
    }
    // ---- pooling phase ----
    __syncthreads();   // everyone done reading ins
    *(float4*)&ins[n * 68 + q * 8 + 0] = make_float4(o[0], o[1], o[2], o[3]);
    *(float4*)&ins[n * 68 + q * 8 + 4] = make_float4(o[4], o[5], o[6], o[7]);
    __syncthreads();
    if (tid < 64) {
        int rows_here = NN - base; if (rows_here > 64) rows_here = 64;
        float accum = 0.f;
        int gcur = sb[0];
        for (int nn = 0; nn < rows_here; nn++) {
            int g = sb[nn];
            if (g != gcur) {
                atomicAdd(&g_pool[gcur * 64 + tid], accum);
                gcur = g; accum = 0.f;
            }
            accum += ins[nn * 68 + tid];
        }
        if (rows_here > 0) atomicAdd(&g_pool[gcur * 64 + tid], accum);
    }
}

// ---------------- final linear 64->10 + softmax ----------------
__global__ void final_kernel(const int* __restrict__ batch,
                             const float* __restrict__ Wl, const float* __restrict__ bl,
                             float* __restrict__ out) {
    __shared__ float Ws[64 * 10];
    __shared__ float bs[10];
    int tid = threadIdx.x;
    for (int i = tid; i < 640; i += 256) Ws[i] = Wl[i];
    if (tid < 10) bs[tid] = bl[tid];
    __syncthreads();
    int g = tid;
    int lo = 0, hi = NN;
    while (lo < hi) { int mid = (lo + hi) >> 1; if (batch[mid] < g) lo = mid + 1; else hi = mid; }
    int lb = lo;
    lo = 0; hi = NN;
    while (lo < hi) { int mid = (lo + hi) >> 1; if (batch[mid] < g + 1) lo = mid + 1; else hi = mid; }
    float cnt = (float)(lo - lb);
    float inv = 1.0f / (3.0f * fmaxf(cnt, 1.0f));
    float logits[10];
#pragma unroll
    for (int o = 0; o < 10; o++) logits[o] = bs[o];
    for (int f = 0; f < 64; f++) {
        float m = g_pool[g * 64 + f] * inv;
#pragma unroll
        for (int o = 0; o < 10; o++) logits[o] += m * Ws[f * 10 + o];
    }
    float mx = logits[0];
#pragma unroll
    for (int o = 1; o < 10; o++) mx = fmaxf(mx, logits[o]);
    float sum = 0.f;
#pragma unroll
    for (int o = 0; o < 10; o++) { logits[o] = expf(logits[o] - mx); sum += logits[o]; }
    float is = 1.0f / sum;
#pragma unroll
    for (int o = 0; o < 10; o++) out[g * 10 + o] = logits[o] * is;
}

// ---------------- launch ----------------
extern "C" void kernel_launch(void* const* d_in, const int* in_sizes, int n_in,
                              void* d_out, int out_size) {
    const float* x    = (const float*)d_in[0];
    const int*   rows = (const int*)d_in[1];
    const int*   cols = (const int*)d_in[2];
    const float* vals = (const float*)d_in[3];
    const int*   batch= (const int*)d_in[4];
    const float* W1 = (const float*)d_in[5];
    const float* b1 = (const float*)d_in[6];
    const float* W2 = (const float*)d_in[7];
    const float* b2 = (const float*)d_in[8];
    const float* W3 = (const float*)d_in[9];
    const float* b3 = (const float*)d_in[10];
    const float* Wl = (const float*)d_in[11];
    const float* bl = (const float*)d_in[12];
    float* out = (float*)d_out;

    zero_kernel<<<(NN + 255) / 256, 256>>>();
    hist_kernel<<<(NE / 4 + 255) / 256, 256>>>((const int4*)rows);
    scanA_kernel<<<NB_SCAN, 512>>>();
    scanB_kernel<<<1, 256>>>();
    scanC_kernel<<<NB_SCAN, 512>>>();
    scatter_kernel<<<(NE / 4 + 255) / 256, 256>>>((const int4*)rows, (const int4*)cols,
                                                  (const float4*)vals);

    pregemm_kernel<<<(NN + 255) / 256, 256>>>(x, W1);

    spmm_l1_kernel<<<(NN + 31) / 32, 256>>>(b1, batch);            // x1 -> xhb, pool
    spmm_lin_kernel<0><<<(NN + 63) / 64, 512>>>(W2, b2, batch);    // x2 -> xha, pool
    spmm_lin_kernel<1><<<(NN + 63) / 64, 512>>>(W3, b3, batch);    // x3 -> pool

    final_kernel<<<1, 256>>>(batch, Wl, bl, out);
}